// round 16
// baseline (speedup 1.0000x reference)
#include <cuda_runtime.h>
#include <cuda_bf16.h>
#include <cuda_fp16.h>
#include <math.h>
#include <stdint.h>

#define B_    32
#define T_    2048
#define DIN   512
#define D_    256
#define OUTD  41
#define L_    3
#define INNER 512
#define BT    (B_*T_)
#define PARTC 1024

typedef __nv_bfloat16 bf16;

// ---------------- scratch ----------------
__device__ bf16   g_xb   [(size_t)BT*DIN];
__device__ bf16   g_h512b[(size_t)BT*DIN];
__device__ __half g_bufA [(size_t)BT*D_];
__device__ float  g_h    [(size_t)BT*D_];
__device__ bf16   g_hb   [(size_t)BT*D_];
__device__ bf16   g_xz   [(size_t)BT*2048];
__device__ bf16   g_xc   [(size_t)BT*1024];
__device__ __half g_dt   [(size_t)BT*1024];
__device__ float  g_part [B_*1024*16];
__device__ __half g_hout [(size_t)BT*128];
// weights
__device__ bf16 g_aWb  [45*512*512];
__device__ bf16 g_cW1b [256*512];
__device__ bf16 g_cW2b [256*256];
__device__ bf16 g_minb [6*1024*256];
__device__ bf16 g_dtWb [6*512*512];
__device__ bf16 g_projb[3*256*512];
__device__ bf16 g_moutA[6*512*256];
__device__ bf16 g_wcomb[3*256*1024];
__device__ bf16 g_wpadb[128*256];

// ---------------- helpers ----------------
__device__ __forceinline__ unsigned s2u(const void* p) {
    return (unsigned)__cvta_generic_to_shared(p);
}
#define CPA(dst, src) asm volatile("cp.async.cg.shared.global [%0], [%1], 16;\n" :: "r"(dst), "l"(src))
#define CP_COMMIT     asm volatile("cp.async.commit_group;\n" ::)
#define CP_WAIT1      asm volatile("cp.async.wait_group 1;\n" ::)
#define CP_WAIT0      asm volatile("cp.async.wait_group 0;\n" ::)
#define LDSMX4(r0,r1,r2,r3,ad) \
    asm volatile("ldmatrix.sync.aligned.m8n8.x4.shared.b16 {%0,%1,%2,%3}, [%4];" \
        : "=r"(r0), "=r"(r1), "=r"(r2), "=r"(r3) : "r"(ad))

__device__ __forceinline__ float4 load4bf(const bf16* p) {
    uint2 r = *(const uint2*)p;
    __nv_bfloat162 a = *(__nv_bfloat162*)&r.x;
    __nv_bfloat162 b = *(__nv_bfloat162*)&r.y;
    float2 fa = __bfloat1622float2(a);
    float2 fb = __bfloat1622float2(b);
    return make_float4(fa.x, fa.y, fb.x, fb.y);
}
__device__ __forceinline__ void store4bf(bf16* p, float a, float b, float c, float d) {
    __nv_bfloat162 lo = __floats2bfloat162_rn(a, b);
    __nv_bfloat162 hi = __floats2bfloat162_rn(c, d);
    uint2 r; r.x = *(uint32_t*)&lo; r.y = *(uint32_t*)&hi;
    *(uint2*)p = r;
}
__device__ __forceinline__ float4 load4hf(const __half* p) {
    uint2 r = *(const uint2*)p;
    __half2 a = *(__half2*)&r.x;
    __half2 b = *(__half2*)&r.y;
    float2 fa = __half22float2(a);
    float2 fb = __half22float2(b);
    return make_float4(fa.x, fa.y, fb.x, fb.y);
}

// ---------------- conversion kernels ----------------
__global__ void cvt_x_k(const float* __restrict__ in, bf16* __restrict__ out)
{
    int idx = blockIdx.x*blockDim.x + threadIdx.x;
    float4 v = *(const float4*)(in + (size_t)idx*4);
    store4bf(out + (size_t)idx*4, v.x, v.y, v.z, v.w);
}

__global__ void tconv_k(const float* __restrict__ in, bf16* __restrict__ out,
                        int R, int C)
{
    __shared__ float t[32][33];
    size_t base = (size_t)blockIdx.z * R * C;
    int c0 = blockIdx.x*32, r0 = blockIdx.y*32;
    #pragma unroll
    for (int i = 0; i < 32; i += 8)
        t[threadIdx.y + i][threadIdx.x] =
            in[base + (size_t)(r0 + threadIdx.y + i)*C + c0 + threadIdx.x];
    __syncthreads();
    #pragma unroll
    for (int i = 0; i < 32; i += 8)
        out[base + (size_t)(c0 + threadIdx.y + i)*R + r0 + threadIdx.x] =
            __float2bfloat16(t[threadIdx.x][threadIdx.y + i]);
}

__global__ void wpad_k(const float* __restrict__ Wo, bf16* __restrict__ wp)
{
    int idx = blockIdx.x*blockDim.x + threadIdx.x;
    int k = idx & 255, n = idx >> 8;
    wp[idx] = __float2bfloat16((n < OUTD) ? Wo[k*OUTD + n] : 0.f);
}

// ---------------- bf16 tensor-core GEMM (128 thr, 64x64 warptiles) ------
#define BM 128
#define BN 128
#define BK 64
#define LSTR 72
#define STAGE (BM*LSTR)
#define NSTG 3
#define SMEM_BYTES (NSTG*2*STAGE*2)

// epi: 0=none, 1=softsign, 3=softplus+fused chunk sums, 4=silu on z-columns
// cty: 0 fp32, 1 bf16, 2 fp16
__global__ void __launch_bounds__(128, 2) tgemm_k(
    const bf16* __restrict__ A, int lda,
    const bf16* __restrict__ W, const float* __restrict__ bias,
    const int* __restrict__ day_ids, long wstride, int bstride,
    void* __restrict__ Cv, int ldc, int coff,
    int K, int N, int epi, int cty, float* __restrict__ part,
    int zA, long zW, int zBias, int zC, int zPart)
{
    extern __shared__ bf16 sm[];
    bf16* Asm = sm;
    bf16* Bsm = sm + NSTG*STAGE;
    __shared__ float sred[256];

    int tid  = threadIdx.x;
    int lane = tid & 31;
    int wid  = tid >> 5;         // 0..3
    int wm   = wid & 1;          // 2 warp-rows of 64
    int wn   = wid >> 1;         // 2 warp-cols of 64
    int n0 = blockIdx.x * BN;
    int m0 = blockIdx.y * BM;
    int zz = blockIdx.z;

    A += (long)zz * zA;
    W += (long)zz * zW;
    if (bias) bias += zz * zBias;
    coff += zz * zC;
    int partoff = zz * zPart;

    const bf16* Wp = W;
    const float* bp = bias;
    if (day_ids) {
        int d = day_ids[m0 >> 11];
        Wp += (long)d * wstride;
        if (bp) bp += (long)d * bstride;
    }

    float acc[4][8][4];
    #pragma unroll
    for (int i = 0; i < 4; i++)
        #pragma unroll
        for (int j = 0; j < 8; j++)
            #pragma unroll
            for (int q = 0; q < 4; q++) acc[i][j][q] = 0.f;

    auto load_tiles = [&](int s, int kc) {
        int k0 = kc << 6;
        #pragma unroll
        for (int it = 0; it < 8; ++it) {
            int idx = tid + it*128;
            int row = idx >> 3, ch = (idx & 7) << 3;
            CPA(s2u(&Asm[s*STAGE + row*LSTR + ch]), A + (long)(m0+row)*lda + k0 + ch);
        }
        #pragma unroll
        for (int it = 0; it < 8; ++it) {
            int idx = tid + it*128;
            int row = idx >> 3, ch = (idx & 7) << 3;
            CPA(s2u(&Bsm[s*STAGE + row*LSTR + ch]), Wp + (long)(n0+row)*K + k0 + ch);
        }
        CP_COMMIT;
    };

    int lrow = (lane & 7) + ((lane >> 3) & 1) * 8;
    int lcol = (lane >> 4) << 3;

    load_tiles(0, 0);
    load_tiles(1, 1);

    int nk = K >> 6;
    int s = 0;
    for (int kc = 0; kc < nk; ++kc) {
        if (kc == nk - 1) { CP_WAIT0; } else { CP_WAIT1; }
        __syncthreads();
        if (kc + 2 < nk) {
            int ws = s + 2; if (ws >= NSTG) ws -= NSTG;
            load_tiles(ws, kc + 2);
        }

        #pragma unroll
        for (int kk = 0; kk < 4; ++kk) {
            uint32_t a[4][4], b[4][4];
            #pragma unroll
            for (int mi = 0; mi < 4; ++mi) {
                unsigned ad = s2u(&Asm[s*STAGE + (wm*64 + mi*16 + lrow)*LSTR + kk*16 + lcol]);
                LDSMX4(a[mi][0], a[mi][1], a[mi][2], a[mi][3], ad);
            }
            #pragma unroll
            for (int np = 0; np < 4; ++np) {
                unsigned ad = s2u(&Bsm[s*STAGE + (wn*64 + np*16 + lrow)*LSTR + kk*16 + lcol]);
                LDSMX4(b[np][0], b[np][1], b[np][2], b[np][3], ad);
            }
            #pragma unroll
            for (int mi = 0; mi < 4; ++mi)
                #pragma unroll
                for (int ni = 0; ni < 8; ++ni) {
                    uint32_t b0 = b[ni>>1][ni&1];
                    uint32_t b1 = b[ni>>1][(ni&1)+2];
                    asm volatile(
                        "mma.sync.aligned.m16n8k16.row.col.f32.bf16.bf16.f32 "
                        "{%0,%1,%2,%3}, {%4,%5,%6,%7}, {%8,%9}, {%0,%1,%2,%3};"
                        : "+f"(acc[mi][ni][0]), "+f"(acc[mi][ni][1]),
                          "+f"(acc[mi][ni][2]), "+f"(acc[mi][ni][3])
                        : "r"(a[mi][0]), "r"(a[mi][1]), "r"(a[mi][2]), "r"(a[mi][3]),
                          "r"(b0), "r"(b1));
                }
        }
        s = (s + 1 >= NSTG) ? 0 : s + 1;
    }

    float csum[8][2];
    #pragma unroll
    for (int ni = 0; ni < 8; ++ni) { csum[ni][0] = 0.f; csum[ni][1] = 0.f; }

    #pragma unroll
    for (int ni = 0; ni < 8; ++ni) {
        int col = n0 + wn*64 + ni*8 + ((lane & 3) << 1);
        float b0 = bp ? bp[col]   : 0.f;
        float b1 = bp ? bp[col+1] : 0.f;
        bool zcol = (epi == 4) && (((col >> 9) & 1) != 0);
        #pragma unroll
        for (int mi = 0; mi < 4; ++mi) {
            #pragma unroll
            for (int half = 0; half < 2; ++half) {
                int orow = m0 + wm*64 + mi*16 + (lane >> 2) + half*8;
                float v0 = acc[mi][ni][half*2+0] + b0;
                float v1 = acc[mi][ni][half*2+1] + b1;
                if (epi == 1) { v0 = v0/(1.f+fabsf(v0)); v1 = v1/(1.f+fabsf(v1)); }
                else if (epi == 3) {
                    v0 = fmaxf(v0,0.f) + __logf(1.f + __expf(-fabsf(v0)));
                    v1 = fmaxf(v1,0.f) + __logf(1.f + __expf(-fabsf(v1)));
                    csum[ni][0] += v0; csum[ni][1] += v1;
                } else if (zcol) {
                    v0 = v0 * __fdividef(1.f, 1.f + __expf(-v0));
                    v1 = v1 * __fdividef(1.f, 1.f + __expf(-v1));
                }
                long off = (long)orow*ldc + coff + col;
                if (cty == 1) {
                    __nv_bfloat162 pk = __floats2bfloat162_rn(v0, v1);
                    *(__nv_bfloat162*)((bf16*)Cv + off) = pk;
                } else if (cty == 2) {
                    __half2 pk = __floats2half2_rn(v0, v1);
                    *(__half2*)((__half*)Cv + off) = pk;
                } else {
                    *(float2*)((float*)Cv + off) = make_float2(v0, v1);
                }
            }
        }
    }

    if (epi == 3) {
        #pragma unroll
        for (int ni = 0; ni < 8; ++ni)
            #pragma unroll
            for (int q = 0; q < 2; ++q)
                #pragma unroll
                for (int o = 4; o < 32; o <<= 1)
                    csum[ni][q] += __shfl_xor_sync(0xffffffffu, csum[ni][q], o);
        if ((lane >> 2) == 0) {
            #pragma unroll
            for (int ni = 0; ni < 8; ++ni)
                #pragma unroll
                for (int q = 0; q < 2; ++q)
                    sred[wid*64 + ni*8 + (lane & 3)*2 + q] = csum[ni][q];
        }
        __syncthreads();
        if (wm == 0) {
            int b = m0 >> 11, chunk = (m0 >> 7) & 15;
            #pragma unroll
            for (int rep = 0; rep < 2; ++rep) {
                int i = lane + rep*32;
                float tot = sred[(wn*2 + 0)*64 + i] + sred[(wn*2 + 1)*64 + i];
                int c = partoff + n0 + wn*64 + i;
                part[((long)(b*PARTC + c) << 4) + chunk] = tot;
            }
        }
    }
}

// ---------------- depthwise conv(4) + SiLU (4 timesteps/thread) ----------
__global__ void conv_silu_k(const bf16* __restrict__ xz,
                            const float* __restrict__ ck,
                            const float* __restrict__ cb,
                            bf16* __restrict__ xc)
{
    int idx = blockIdx.x*blockDim.x + threadIdx.x;   // BT/4 * 256
    int cq   = idx & 255;
    int btt4 = idx >> 8;
    int t0   = (btt4 & 511) << 2;
    int bq   = btt4 >> 9;
    int c    = cq << 2;
    int dir  = c >> 9;
    int cc   = c & 511;
    long row = (long)(bq*2048 + t0);
    const bf16* base = xz + row*2048 + dir*1024 + cc;

    float4 zf = make_float4(0,0,0,0);
    float4 r[7];   // dir0: rows t0-2..t0+4 ; dir1: rows t0-1..t0+5
    if (dir == 0) {
        r[0] = (t0 >= 2)    ? load4bf(base - 4096) : zf;
        r[1] = (t0 >= 1)    ? load4bf(base - 2048) : zf;
        r[2] =                load4bf(base);
        r[3] =                load4bf(base + 2048);
        r[4] =                load4bf(base + 4096);   // t0+2 <= 2046 always (t0<=2044)
        r[5] =                load4bf(base + 6144);   // t0+3 <= 2047 always
        r[6] = (t0 <= 2040) ? load4bf(base + 8192) : zf;
    } else {
        r[0] = (t0 >= 1)    ? load4bf(base - 2048) : zf;
        r[1] =                load4bf(base);
        r[2] =                load4bf(base + 2048);
        r[3] =                load4bf(base + 4096);
        r[4] =                load4bf(base + 6144);
        r[5] = (t0 <= 2040) ? load4bf(base + 8192) : zf;
        r[6] = (t0 <= 2040) ? load4bf(base + 10240) : zf;
    }
    float4 bias = *(const float4*)(cb + dir*512 + cc);
    const float* bi = (const float*)&bias;
    #pragma unroll
    for (int j = 0; j < 4; ++j) {            // output timestep t0+j
        float o[4];
        #pragma unroll
        for (int i = 0; i < 4; ++i) {
            float4 kk = *(const float4*)(ck + (dir*512 + cc + i)*4);
            const float* p0 = (const float*)&r[j+0];
            const float* p1 = (const float*)&r[j+1];
            const float* p2 = (const float*)&r[j+2];
            const float* p3 = (const float*)&r[j+3];
            float sv;
            if (dir == 0)   // k0*X[t-2]+k1*X[t-1]+k2*X[t]+k3*X[t+1]
                sv = bi[i] + p0[i]*kk.x + p1[i]*kk.y + p2[i]*kk.z + p3[i]*kk.w;
            else            // k0*X[t+2]+k1*X[t+1]+k2*X[t]+k3*X[t-1]
                sv = bi[i] + p3[i]*kk.x + p2[i]*kk.y + p1[i]*kk.z + p0[i]*kk.w;
            o[i] = sv * __fdividef(1.f, 1.f + __expf(-sv));
        }
        store4bf(xc + (row+j)*1024 + c, o[0], o[1], o[2], o[3]);
    }
}

// ---------------- scan (z pre-silu'd in GEMM epilogue) ----------------
__global__ void scan3_k(const __half* __restrict__ dt, const bf16* __restrict__ xz,
                        bf16* __restrict__ xc, const float* __restrict__ part)
{
    int idx = blockIdx.x*blockDim.x + threadIdx.x;
    int cq = idx & 255, chunk = (idx >> 8) & 15, b = idx >> 12;
    int c = cq << 2, dir = c >> 9, cc = c & 511;

    float offv[4];
    #pragma unroll
    for (int q = 0; q < 4; ++q) {
        const float* pp = part + ((long)(b*1024 + c + q) << 4);
        float sv = 0.f;
        #pragma unroll
        for (int ch = 0; ch < 16; ++ch) {
            bool take = dir ? (ch > chunk) : (ch < chunk);
            if (take) sv += pp[ch];
        }
        offv[q] = sv;
    }
    float4 accv = make_float4(offv[0], offv[1], offv[2], offv[3]);

    int row0 = b*2048 + chunk*128;
    int rstart = dir ? (row0 + 127) : row0;
    long dstep = dir ? -1024 : 1024;
    long zstep = dir ? -2048 : 2048;
    long dtb = (long)rstart*1024 + c;
    long zb  = (long)rstart*2048 + dir*1024 + 512 + cc;

    #pragma unroll 4
    for (int i = 0; i < 128; i++) {
        float4 d = load4hf(dt + dtb);
        float4 z = load4bf(xz + zb);
        float4 u = load4bf(xc + dtb);
        accv.x += d.x; accv.y += d.y; accv.z += d.z; accv.w += d.w;
        float o[4];
        float* ap = (float*)&accv; float* zp = (float*)&z; float* up = (float*)&u;
        #pragma unroll
        for (int q = 0; q < 4; ++q) {
            float w = __expf(-0.1f * ap[q]);
            o[q] = up[q] * w * zp[q];
        }
        store4bf(xc + dtb, o[0], o[1], o[2], o[3]);
        dtb += dstep; zb += zstep;
    }
}

// ---------------- warp-per-row LayerNorm ----------------
__device__ __forceinline__ float warp_sum(float v) {
    #pragma unroll
    for (int o = 16; o; o >>= 1) v += __shfl_xor_sync(0xffffffffu, v, o);
    return v;
}

__global__ void ln_k(const __half* __restrict__ X, const float* __restrict__ R,
                     const float* __restrict__ s, const float* __restrict__ bb,
                     float* __restrict__ Y, bf16* __restrict__ Yb, int do_silu)
{
    int w = threadIdx.x >> 5, lane = threadIdx.x & 31;
    long row = (long)blockIdx.x*8 + w;
    const __half* xp = X + row*256;
    float v[8];
    #pragma unroll
    for (int q = 0; q < 2; q++) {
        float4 t = load4hf(xp + q*128 + lane*4);
        v[q*4+0]=t.x; v[q*4+1]=t.y; v[q*4+2]=t.z; v[q*4+3]=t.w;
    }
    if (R) {
        const float* rp = R + row*256;
        #pragma unroll
        for (int q = 0; q < 2; q++) {
            float4 t = *(const float4*)(rp + q*128 + lane*4);
            v[q*4+0]+=t.x; v[q*4+1]+=t.y; v[q*4+2]+=t.z; v[q*4+3]+=t.w;
        }
    }
    float sum = 0.f;
    #pragma unroll
    for (int i = 0; i < 8; i++) sum += v[i];
    float m = warp_sum(sum) * (1.f/256.f);
    float sq = 0.f;
    #pragma unroll
    for (int i = 0; i < 8; i++) { float d = v[i]-m; sq += d*d; }
    float inv = rsqrtf(warp_sum(sq)*(1.f/256.f) + 1e-5f);
    #pragma unroll
    for (int q = 0; q < 2; q++) {
        int col = q*128 + lane*4;
        float4 sc = *(const float4*)(s + col);
        float4 bc = *(const float4*)(bb + col);
        float o[4];
        #pragma unroll
        for (int i = 0; i < 4; i++) {
            float y = (v[q*4+i]-m)*inv * ((float*)&sc)[i] + ((float*)&bc)[i];
            if (do_silu) y = y * __fdividef(1.f, 1.f + __expf(-y));
            o[i] = y;
        }
        if (Y) *(float4*)(Y + row*256 + col) = make_float4(o[0],o[1],o[2],o[3]);
        store4bf(Yb + row*256 + col, o[0], o[1], o[2], o[3]);
    }
}

// ---------------- head log-softmax (fp16 input) ----------------
__global__ void lsm_k(const __half* __restrict__ HP, const float* __restrict__ bo,
                      float* __restrict__ out)
{
    int w = threadIdx.x >> 5, lane = threadIdx.x & 31;
    long row = (long)blockIdx.x*8 + w;
    const __half* hp = HP + row*128;
    float v0 = __half2float(hp[lane]) + bo[lane];
    float v1 = (lane < 9) ? __half2float(hp[lane+32]) + bo[lane+32] : -INFINITY;
    float mx = fmaxf(v0, v1);
    #pragma unroll
    for (int o = 16; o; o >>= 1) mx = fmaxf(mx, __shfl_xor_sync(0xffffffffu, mx, o));
    float se = __expf(v0 - mx) + (lane < 9 ? __expf(v1 - mx) : 0.f);
    se = warp_sum(se);
    float lse = mx + logf(se);
    out[row*OUTD + lane] = v0 - lse;
    if (lane < 9) out[row*OUTD + lane + 32] = v1 - lse;
}

// ---------------- host ----------------
extern "C" void kernel_launch(void* const* d_in, const int* in_sizes, int n_in,
                              void* d_out, int out_size)
{
    (void)in_sizes; (void)n_in; (void)out_size;
    const float* x         = (const float*)d_in[0];
    const int*   day_ids   = (const int*)  d_in[1];
    const float* adapter_W = (const float*)d_in[2];
    const float* adapter_b = (const float*)d_in[3];
    const float* cW1   = (const float*)d_in[4];
    const float* cb1   = (const float*)d_in[5];
    const float* cln1s = (const float*)d_in[6];
    const float* cln1b = (const float*)d_in[7];
    const float* cW2   = (const float*)d_in[8];
    const float* cb2   = (const float*)d_in[9];
    const float* cln2s = (const float*)d_in[10];
    const float* cln2b = (const float*)d_in[11];
    const float* m_in    = (const float*)d_in[12];
    const float* m_convK = (const float*)d_in[13];
    const float* m_convB = (const float*)d_in[14];
    const float* m_dtW   = (const float*)d_in[15];
    const float* m_dtB   = (const float*)d_in[16];
    const float* m_out   = (const float*)d_in[17];
    const float* proj_W  = (const float*)d_in[18];
    const float* proj_b  = (const float*)d_in[19];
    const float* norm_s  = (const float*)d_in[20];
    const float* norm_b  = (const float*)d_in[21];
    const float* outW    = (const float*)d_in[22];
    const float* outb    = (const float*)d_in[23];
    float* out = (float*)d_out;

    static bf16 *p_xb=nullptr, *p_h512b=nullptr, *p_hb=nullptr, *p_xz=nullptr,
                *p_xc=nullptr, *p_aWb=nullptr, *p_cW1b=nullptr, *p_cW2b=nullptr,
                *p_minb=nullptr, *p_dtWb=nullptr, *p_projb=nullptr, *p_moutA=nullptr,
                *p_wcomb=nullptr, *p_wpadb=nullptr;
    static __half *p_dt=nullptr, *p_bufA=nullptr, *p_hout=nullptr;
    static float *p_h=nullptr, *p_part=nullptr;
    if (!p_xb) {
        cudaGetSymbolAddress((void**)&p_xb,    g_xb);
        cudaGetSymbolAddress((void**)&p_h512b, g_h512b);
        cudaGetSymbolAddress((void**)&p_bufA,  g_bufA);
        cudaGetSymbolAddress((void**)&p_h,     g_h);
        cudaGetSymbolAddress((void**)&p_hb,    g_hb);
        cudaGetSymbolAddress((void**)&p_xz,    g_xz);
        cudaGetSymbolAddress((void**)&p_xc,    g_xc);
        cudaGetSymbolAddress((void**)&p_dt,    g_dt);
        cudaGetSymbolAddress((void**)&p_part,  g_part);
        cudaGetSymbolAddress((void**)&p_hout,  g_hout);
        cudaGetSymbolAddress((void**)&p_aWb,   g_aWb);
        cudaGetSymbolAddress((void**)&p_cW1b,  g_cW1b);
        cudaGetSymbolAddress((void**)&p_cW2b,  g_cW2b);
        cudaGetSymbolAddress((void**)&p_minb,  g_minb);
        cudaGetSymbolAddress((void**)&p_dtWb,  g_dtWb);
        cudaGetSymbolAddress((void**)&p_projb, g_projb);
        cudaGetSymbolAddress((void**)&p_moutA, g_moutA);
        cudaGetSymbolAddress((void**)&p_wcomb, g_wcomb);
        cudaGetSymbolAddress((void**)&p_wpadb, g_wpadb);
        cudaFuncSetAttribute(tgemm_k, cudaFuncAttributeMaxDynamicSharedMemorySize,
                             SMEM_BYTES);
    }

    auto gemm = [&](const bf16* A, int lda,
                    const bf16* W, const float* bias,
                    const int* days, long wstride, int bstride,
                    void* C, int ldc, int coff,
                    int M, int K, int N, int epi, int cty,
                    int nz, int zA, long zW, int zBias, int zC, int zPart) {
        dim3 grid(N/BN, M/BM, nz);
        tgemm_k<<<grid, 128, SMEM_BYTES>>>(A, lda, W, bias, days, wstride, bstride,
                                           C, ldc, coff, K, N, epi, cty, p_part,
                                           zA, zW, zBias, zC, zPart);
    };

    // ---- conversions ----
    dim3 tb(32, 8);
    cvt_x_k<<<(BT*DIN/4)/256, 256>>>(x, p_xb);
    tconv_k<<<dim3(16,16,45), tb>>>(adapter_W, p_aWb, 512, 512);
    tconv_k<<<dim3(8,16,1),   tb>>>(cW1, p_cW1b, 512, 256);
    tconv_k<<<dim3(8,8,1),    tb>>>(cW2, p_cW2b, 256, 256);
    tconv_k<<<dim3(32,8,6),   tb>>>(m_in, p_minb, 256, 1024);
    tconv_k<<<dim3(16,16,6),  tb>>>(m_dtW, p_dtWb, 512, 512);
    tconv_k<<<dim3(8,16,3),   tb>>>(proj_W, p_projb, 512, 256);
    cvt_x_k<<<(6*512*256/4)/256, 256>>>(m_out, p_moutA);
    wpad_k<<<128, 256>>>(outW, p_wpadb);

    // ---- fused weight products ----
    for (int l = 0; l < L_; ++l)
        for (int dir = 0; dir < 2; ++dir)
            gemm(p_projb + (long)l*256*512 + dir*256, 512,
                 p_moutA + (long)(l*2+dir)*512*256, nullptr, nullptr, 0, 0,
                 p_wcomb + (long)l*256*1024, 1024, dir*512,
                 256, 256, 512, 0, 1, 1, 0,0,0,0,0);

    // 1) adapter
    gemm(p_xb, 512, p_aWb, adapter_b, day_ids, 512L*512, 512,
         p_h512b, 512, 0, BT, 512, 512, 1, 1, 1, 0,0,0,0,0);
    // 2) stem
    gemm(p_h512b, 512, p_cW1b, cb1, nullptr,0,0, p_bufA, 256, 0,
         BT, 512, 256, 0, 2, 1, 0,0,0,0,0);
    ln_k<<<BT/8, 256>>>(p_bufA, nullptr, cln1s, cln1b, nullptr, p_hb, 1);
    gemm(p_hb, 256, p_cW2b, cb2, nullptr,0,0, p_bufA, 256, 0,
         BT, 256, 256, 0, 2, 1, 0,0,0,0,0);
    ln_k<<<BT/8, 256>>>(p_bufA, nullptr, cln2s, cln2b, p_h, p_hb, 1);

    // 3) layers
    for (int l = 0; l < L_; ++l) {
        gemm(p_hb, 256, p_minb + (long)l*2048*256, nullptr, nullptr,0,0,
             p_xz, 2048, 0, BT, 256, 2048, 4, 1, 1, 0,0,0,0,0);
        conv_silu_k<<<(BT*64)/256, 256>>>(p_xz,
            m_convK + (long)l*2*512*4, m_convB + (long)l*2*512, p_xc);
        gemm(p_xc, 1024, p_dtWb + (long)l*2*512*512, m_dtB + (long)l*1024,
             nullptr,0,0, p_dt, 1024, 0, BT, 512, 512, 3, 2,
             2, 512, 512L*512, 512, 512, 512);
        scan3_k<<<512, 256>>>(p_dt, p_xz, p_xc, p_part);
        gemm(p_xc, 1024, p_wcomb + (long)l*256*1024, proj_b + l*256,
             nullptr,0,0, p_bufA, 256, 0, BT, 1024, 256, 0, 2, 1, 0,0,0,0,0);
        ln_k<<<BT/8, 256>>>(p_bufA, p_h, norm_s + l*256, norm_b + l*256,
                            p_h, p_hb, 0);
    }

    // 4) head
    gemm(p_hb, 256, p_wpadb, nullptr, nullptr,0,0, p_hout, 128, 0,
         BT, 256, 128, 0, 2, 1, 0,0,0,0,0);
    lsm_k<<<BT/8, 256>>>(p_hout, outb, out);
}

// round 17
// speedup vs baseline: 1.0750x; 1.0750x over previous
#include <cuda_runtime.h>
#include <cuda_bf16.h>
#include <cuda_fp16.h>
#include <math.h>
#include <stdint.h>

#define B_    32
#define T_    2048
#define DIN   512
#define D_    256
#define OUTD  41
#define L_    3
#define INNER 512
#define BT    (B_*T_)
#define PARTC 1024

typedef __nv_bfloat16 bf16;

// ---------------- scratch ----------------
__device__ bf16   g_xb   [(size_t)BT*DIN];
__device__ bf16   g_h512b[(size_t)BT*DIN];
__device__ __half g_bufA [(size_t)BT*D_];
__device__ float  g_h    [(size_t)BT*D_];
__device__ bf16   g_hb   [(size_t)BT*D_];
__device__ bf16   g_xz   [(size_t)BT*2048];
__device__ bf16   g_xc   [(size_t)BT*1024];
__device__ __half g_dt   [(size_t)BT*1024];
__device__ float  g_part [B_*1024*16];
__device__ __half g_hout [(size_t)BT*128];
// weights
__device__ bf16 g_aWb  [45*512*512];
__device__ bf16 g_cW1b [256*512];
__device__ bf16 g_cW2b [256*256];
__device__ bf16 g_minb [6*1024*256];
__device__ bf16 g_dtWb [6*512*512];
__device__ bf16 g_projb[3*256*512];
__device__ bf16 g_moutA[6*512*256];
__device__ bf16 g_wcomb[3*256*1024];
__device__ bf16 g_wpadb[128*256];

// ---------------- helpers ----------------
__device__ __forceinline__ unsigned s2u(const void* p) {
    return (unsigned)__cvta_generic_to_shared(p);
}
#define CPA(dst, src) asm volatile("cp.async.cg.shared.global [%0], [%1], 16;\n" :: "r"(dst), "l"(src))
#define CP_COMMIT     asm volatile("cp.async.commit_group;\n" ::)
#define CP_WAIT1      asm volatile("cp.async.wait_group 1;\n" ::)
#define CP_WAIT0      asm volatile("cp.async.wait_group 0;\n" ::)
#define LDSMX4(r0,r1,r2,r3,ad) \
    asm volatile("ldmatrix.sync.aligned.m8n8.x4.shared.b16 {%0,%1,%2,%3}, [%4];" \
        : "=r"(r0), "=r"(r1), "=r"(r2), "=r"(r3) : "r"(ad))

__device__ __forceinline__ float4 load4bf(const bf16* p) {
    uint2 r = *(const uint2*)p;
    __nv_bfloat162 a = *(__nv_bfloat162*)&r.x;
    __nv_bfloat162 b = *(__nv_bfloat162*)&r.y;
    float2 fa = __bfloat1622float2(a);
    float2 fb = __bfloat1622float2(b);
    return make_float4(fa.x, fa.y, fb.x, fb.y);
}
__device__ __forceinline__ void store4bf(bf16* p, float a, float b, float c, float d) {
    __nv_bfloat162 lo = __floats2bfloat162_rn(a, b);
    __nv_bfloat162 hi = __floats2bfloat162_rn(c, d);
    uint2 r; r.x = *(uint32_t*)&lo; r.y = *(uint32_t*)&hi;
    *(uint2*)p = r;
}
__device__ __forceinline__ float4 load4hf(const __half* p) {
    uint2 r = *(const uint2*)p;
    __half2 a = *(__half2*)&r.x;
    __half2 b = *(__half2*)&r.y;
    float2 fa = __half22float2(a);
    float2 fb = __half22float2(b);
    return make_float4(fa.x, fa.y, fb.x, fb.y);
}

// ---------------- conversion kernels ----------------
__global__ void cvt_x_k(const float* __restrict__ in, bf16* __restrict__ out)
{
    int idx = blockIdx.x*blockDim.x + threadIdx.x;
    float4 v = *(const float4*)(in + (size_t)idx*4);
    store4bf(out + (size_t)idx*4, v.x, v.y, v.z, v.w);
}

__global__ void tconv_k(const float* __restrict__ in, bf16* __restrict__ out,
                        int R, int C)
{
    __shared__ float t[32][33];
    size_t base = (size_t)blockIdx.z * R * C;
    int c0 = blockIdx.x*32, r0 = blockIdx.y*32;
    #pragma unroll
    for (int i = 0; i < 32; i += 8)
        t[threadIdx.y + i][threadIdx.x] =
            in[base + (size_t)(r0 + threadIdx.y + i)*C + c0 + threadIdx.x];
    __syncthreads();
    #pragma unroll
    for (int i = 0; i < 32; i += 8)
        out[base + (size_t)(c0 + threadIdx.y + i)*R + r0 + threadIdx.x] =
            __float2bfloat16(t[threadIdx.x][threadIdx.y + i]);
}

__global__ void wpad_k(const float* __restrict__ Wo, bf16* __restrict__ wp)
{
    int idx = blockIdx.x*blockDim.x + threadIdx.x;
    int k = idx & 255, n = idx >> 8;
    wp[idx] = __float2bfloat16((n < OUTD) ? Wo[k*OUTD + n] : 0.f);
}

// ---------------- bf16 tensor-core GEMM (R15: 256thr, BK=64, 3-stage) ----
#define BM 128
#define BN 128
#define BK 64
#define LSTR 72
#define STAGE (BM*LSTR)
#define NSTG 3
#define SMEM_BYTES (NSTG*2*STAGE*2)

// epi: 0=none, 1=softsign, 3=softplus+fused chunk sums, 4=silu on z-columns
// cty: 0 fp32, 1 bf16, 2 fp16
__global__ void __launch_bounds__(256, 2) tgemm_k(
    const bf16* __restrict__ A, int lda,
    const bf16* __restrict__ W, const float* __restrict__ bias,
    const int* __restrict__ day_ids, long wstride, int bstride,
    void* __restrict__ Cv, int ldc, int coff,
    int K, int N, int epi, int cty, float* __restrict__ part,
    int zA, long zW, int zBias, int zC, int zPart)
{
    extern __shared__ bf16 sm[];
    bf16* Asm = sm;
    bf16* Bsm = sm + NSTG*STAGE;
    __shared__ float sred[256];

    int tid  = threadIdx.x;
    int lane = tid & 31;
    int wid  = tid >> 5;
    int wm   = wid & 1;
    int wn   = wid >> 1;
    int n0 = blockIdx.x * BN;
    int m0 = blockIdx.y * BM;
    int zz = blockIdx.z;

    A += (long)zz * zA;
    W += (long)zz * zW;
    if (bias) bias += zz * zBias;
    coff += zz * zC;
    int partoff = zz * zPart;

    const bf16* Wp = W;
    const float* bp = bias;
    if (day_ids) {
        int d = day_ids[m0 >> 11];
        Wp += (long)d * wstride;
        if (bp) bp += (long)d * bstride;
    }

    float acc[4][4][4];
    #pragma unroll
    for (int i = 0; i < 4; i++)
        #pragma unroll
        for (int j = 0; j < 4; j++)
            #pragma unroll
            for (int q = 0; q < 4; q++) acc[i][j][q] = 0.f;

    auto load_tiles = [&](int s, int kc) {
        int k0 = kc << 6;
        #pragma unroll
        for (int it = 0; it < 4; ++it) {
            int idx = tid + it*256;
            int row = idx >> 3, ch = (idx & 7) << 3;
            CPA(s2u(&Asm[s*STAGE + row*LSTR + ch]), A + (long)(m0+row)*lda + k0 + ch);
        }
        #pragma unroll
        for (int it = 0; it < 4; ++it) {
            int idx = tid + it*256;
            int row = idx >> 3, ch = (idx & 7) << 3;
            CPA(s2u(&Bsm[s*STAGE + row*LSTR + ch]), Wp + (long)(n0+row)*K + k0 + ch);
        }
        CP_COMMIT;
    };

    int lrow = (lane & 7) + ((lane >> 3) & 1) * 8;
    int lcol = (lane >> 4) << 3;

    load_tiles(0, 0);
    load_tiles(1, 1);

    int nk = K >> 6;
    int s = 0;
    for (int kc = 0; kc < nk; ++kc) {
        if (kc == nk - 1) { CP_WAIT0; } else { CP_WAIT1; }
        __syncthreads();
        if (kc + 2 < nk) {
            int ws = s + 2; if (ws >= NSTG) ws -= NSTG;
            load_tiles(ws, kc + 2);
        }

        #pragma unroll
        for (int kk = 0; kk < 4; ++kk) {
            uint32_t a[4][4], b[2][4];
            #pragma unroll
            for (int mi = 0; mi < 4; ++mi) {
                unsigned ad = s2u(&Asm[s*STAGE + (wm*64 + mi*16 + lrow)*LSTR + kk*16 + lcol]);
                LDSMX4(a[mi][0], a[mi][1], a[mi][2], a[mi][3], ad);
            }
            #pragma unroll
            for (int np = 0; np < 2; ++np) {
                unsigned ad = s2u(&Bsm[s*STAGE + (wn*32 + np*16 + lrow)*LSTR + kk*16 + lcol]);
                LDSMX4(b[np][0], b[np][1], b[np][2], b[np][3], ad);
            }
            #pragma unroll
            for (int mi = 0; mi < 4; ++mi)
                #pragma unroll
                for (int ni = 0; ni < 4; ++ni) {
                    uint32_t b0 = b[ni>>1][ni&1];
                    uint32_t b1 = b[ni>>1][(ni&1)+2];
                    asm volatile(
                        "mma.sync.aligned.m16n8k16.row.col.f32.bf16.bf16.f32 "
                        "{%0,%1,%2,%3}, {%4,%5,%6,%7}, {%8,%9}, {%0,%1,%2,%3};"
                        : "+f"(acc[mi][ni][0]), "+f"(acc[mi][ni][1]),
                          "+f"(acc[mi][ni][2]), "+f"(acc[mi][ni][3])
                        : "r"(a[mi][0]), "r"(a[mi][1]), "r"(a[mi][2]), "r"(a[mi][3]),
                          "r"(b0), "r"(b1));
                }
        }
        s = (s + 1 >= NSTG) ? 0 : s + 1;
    }

    float csum[4][2];
    #pragma unroll
    for (int ni = 0; ni < 4; ++ni) { csum[ni][0] = 0.f; csum[ni][1] = 0.f; }

    #pragma unroll
    for (int ni = 0; ni < 4; ++ni) {
        int col = n0 + wn*32 + ni*8 + ((lane & 3) << 1);
        float b0 = bp ? bp[col]   : 0.f;
        float b1 = bp ? bp[col+1] : 0.f;
        bool zcol = (epi == 4) && (((col >> 9) & 1) != 0);
        #pragma unroll
        for (int mi = 0; mi < 4; ++mi) {
            #pragma unroll
            for (int half = 0; half < 2; ++half) {
                int orow = m0 + wm*64 + mi*16 + (lane >> 2) + half*8;
                float v0 = acc[mi][ni][half*2+0] + b0;
                float v1 = acc[mi][ni][half*2+1] + b1;
                if (epi == 1) { v0 = v0/(1.f+fabsf(v0)); v1 = v1/(1.f+fabsf(v1)); }
                else if (epi == 3) {
                    v0 = fmaxf(v0,0.f) + __logf(1.f + __expf(-fabsf(v0)));
                    v1 = fmaxf(v1,0.f) + __logf(1.f + __expf(-fabsf(v1)));
                    csum[ni][0] += v0; csum[ni][1] += v1;
                } else if (zcol) {
                    v0 = v0 * __fdividef(1.f, 1.f + __expf(-v0));
                    v1 = v1 * __fdividef(1.f, 1.f + __expf(-v1));
                }
                long off = (long)orow*ldc + coff + col;
                if (cty == 1) {
                    __nv_bfloat162 pk = __floats2bfloat162_rn(v0, v1);
                    *(__nv_bfloat162*)((bf16*)Cv + off) = pk;
                } else if (cty == 2) {
                    __half2 pk = __floats2half2_rn(v0, v1);
                    *(__half2*)((__half*)Cv + off) = pk;
                } else {
                    *(float2*)((float*)Cv + off) = make_float2(v0, v1);
                }
            }
        }
    }

    if (epi == 3) {
        #pragma unroll
        for (int ni = 0; ni < 4; ++ni)
            #pragma unroll
            for (int q = 0; q < 2; ++q)
                #pragma unroll
                for (int o = 4; o < 32; o <<= 1)
                    csum[ni][q] += __shfl_xor_sync(0xffffffffu, csum[ni][q], o);
        if ((lane >> 2) == 0) {
            #pragma unroll
            for (int ni = 0; ni < 4; ++ni)
                #pragma unroll
                for (int q = 0; q < 2; ++q)
                    sred[(((wm*4 + wn)*4 + ni)*4 + lane)*2 + q] = csum[ni][q];
        }
        __syncthreads();
        if (wm == 0 && (lane >> 2) == 0) {
            int b = m0 >> 11, chunk = (m0 >> 7) & 15;
            #pragma unroll
            for (int ni = 0; ni < 4; ++ni)
                #pragma unroll
                for (int q = 0; q < 2; ++q) {
                    int c = partoff + n0 + wn*32 + ni*8 + lane*2 + q;
                    float tot = sred[((wn*4 + ni)*4 + lane)*2 + q]
                              + sred[(((4 + wn)*4 + ni)*4 + lane)*2 + q];
                    part[((long)(b*PARTC + c) << 4) + chunk] = tot;
                }
        }
    }
}

// ---------------- depthwise conv(4) + SiLU (4 timesteps/thread) ----------
__global__ void conv_silu_k(const bf16* __restrict__ xz,
                            const float* __restrict__ ck,
                            const float* __restrict__ cb,
                            bf16* __restrict__ xc)
{
    int idx = blockIdx.x*blockDim.x + threadIdx.x;   // BT/4 * 256
    int cq   = idx & 255;
    int btt4 = idx >> 8;
    int t0   = (btt4 & 511) << 2;
    int bq   = btt4 >> 9;
    int c    = cq << 2;
    int dir  = c >> 9;
    int cc   = c & 511;
    long row = (long)(bq*2048 + t0);
    const bf16* base = xz + row*2048 + dir*1024 + cc;

    float4 zf = make_float4(0,0,0,0);
    float4 r[7];
    if (dir == 0) {
        r[0] = (t0 >= 2)    ? load4bf(base - 4096) : zf;
        r[1] = (t0 >= 1)    ? load4bf(base - 2048) : zf;
        r[2] =                load4bf(base);
        r[3] =                load4bf(base + 2048);
        r[4] =                load4bf(base + 4096);
        r[5] =                load4bf(base + 6144);
        r[6] = (t0 <= 2040) ? load4bf(base + 8192) : zf;
    } else {
        r[0] = (t0 >= 1)    ? load4bf(base - 2048) : zf;
        r[1] =                load4bf(base);
        r[2] =                load4bf(base + 2048);
        r[3] =                load4bf(base + 4096);
        r[4] =                load4bf(base + 6144);
        r[5] = (t0 <= 2040) ? load4bf(base + 8192) : zf;
        r[6] = (t0 <= 2040) ? load4bf(base + 10240) : zf;
    }
    float4 bias = *(const float4*)(cb + dir*512 + cc);
    const float* bi = (const float*)&bias;
    #pragma unroll
    for (int j = 0; j < 4; ++j) {
        float o[4];
        #pragma unroll
        for (int i = 0; i < 4; ++i) {
            float4 kk = *(const float4*)(ck + (dir*512 + cc + i)*4);
            const float* p0 = (const float*)&r[j+0];
            const float* p1 = (const float*)&r[j+1];
            const float* p2 = (const float*)&r[j+2];
            const float* p3 = (const float*)&r[j+3];
            float sv;
            if (dir == 0)
                sv = bi[i] + p0[i]*kk.x + p1[i]*kk.y + p2[i]*kk.z + p3[i]*kk.w;
            else
                sv = bi[i] + p3[i]*kk.x + p2[i]*kk.y + p1[i]*kk.z + p0[i]*kk.w;
            o[i] = sv * __fdividef(1.f, 1.f + __expf(-sv));
        }
        store4bf(xc + (row+j)*1024 + c, o[0], o[1], o[2], o[3]);
    }
}

// ---------------- scan (z pre-silu'd in GEMM epilogue) ----------------
__global__ void scan3_k(const __half* __restrict__ dt, const bf16* __restrict__ xz,
                        bf16* __restrict__ xc, const float* __restrict__ part)
{
    int idx = blockIdx.x*blockDim.x + threadIdx.x;
    int cq = idx & 255, chunk = (idx >> 8) & 15, b = idx >> 12;
    int c = cq << 2, dir = c >> 9, cc = c & 511;

    float offv[4];
    #pragma unroll
    for (int q = 0; q < 4; ++q) {
        const float* pp = part + ((long)(b*1024 + c + q) << 4);
        float sv = 0.f;
        #pragma unroll
        for (int ch = 0; ch < 16; ++ch) {
            bool take = dir ? (ch > chunk) : (ch < chunk);
            if (take) sv += pp[ch];
        }
        offv[q] = sv;
    }
    float4 accv = make_float4(offv[0], offv[1], offv[2], offv[3]);

    int row0 = b*2048 + chunk*128;
    int rstart = dir ? (row0 + 127) : row0;
    long dstep = dir ? -1024 : 1024;
    long zstep = dir ? -2048 : 2048;
    long dtb = (long)rstart*1024 + c;
    long zb  = (long)rstart*2048 + dir*1024 + 512 + cc;

    #pragma unroll 4
    for (int i = 0; i < 128; i++) {
        float4 d = load4hf(dt + dtb);
        float4 z = load4bf(xz + zb);
        float4 u = load4bf(xc + dtb);
        accv.x += d.x; accv.y += d.y; accv.z += d.z; accv.w += d.w;
        float o[4];
        float* ap = (float*)&accv; float* zp = (float*)&z; float* up = (float*)&u;
        #pragma unroll
        for (int q = 0; q < 4; ++q) {
            float w = __expf(-0.1f * ap[q]);
            o[q] = up[q] * w * zp[q];
        }
        store4bf(xc + dtb, o[0], o[1], o[2], o[3]);
        dtb += dstep; zb += zstep;
    }
}

// ---------------- warp-per-row LayerNorm ----------------
__device__ __forceinline__ float warp_sum(float v) {
    #pragma unroll
    for (int o = 16; o; o >>= 1) v += __shfl_xor_sync(0xffffffffu, v, o);
    return v;
}

__global__ void ln_k(const __half* __restrict__ X, const float* __restrict__ R,
                     const float* __restrict__ s, const float* __restrict__ bb,
                     float* __restrict__ Y, bf16* __restrict__ Yb, int do_silu)
{
    int w = threadIdx.x >> 5, lane = threadIdx.x & 31;
    long row = (long)blockIdx.x*8 + w;
    const __half* xp = X + row*256;
    float v[8];
    #pragma unroll
    for (int q = 0; q < 2; q++) {
        float4 t = load4hf(xp + q*128 + lane*4);
        v[q*4+0]=t.x; v[q*4+1]=t.y; v[q*4+2]=t.z; v[q*4+3]=t.w;
    }
    if (R) {
        const float* rp = R + row*256;
        #pragma unroll
        for (int q = 0; q < 2; q++) {
            float4 t = *(const float4*)(rp + q*128 + lane*4);
            v[q*4+0]+=t.x; v[q*4+1]+=t.y; v[q*4+2]+=t.z; v[q*4+3]+=t.w;
        }
    }
    float sum = 0.f;
    #pragma unroll
    for (int i = 0; i < 8; i++) sum += v[i];
    float m = warp_sum(sum) * (1.f/256.f);
    float sq = 0.f;
    #pragma unroll
    for (int i = 0; i < 8; i++) { float d = v[i]-m; sq += d*d; }
    float inv = rsqrtf(warp_sum(sq)*(1.f/256.f) + 1e-5f);
    #pragma unroll
    for (int q = 0; q < 2; q++) {
        int col = q*128 + lane*4;
        float4 sc = *(const float4*)(s + col);
        float4 bc = *(const float4*)(bb + col);
        float o[4];
        #pragma unroll
        for (int i = 0; i < 4; i++) {
            float y = (v[q*4+i]-m)*inv * ((float*)&sc)[i] + ((float*)&bc)[i];
            if (do_silu) y = y * __fdividef(1.f, 1.f + __expf(-y));
            o[i] = y;
        }
        if (Y) *(float4*)(Y + row*256 + col) = make_float4(o[0],o[1],o[2],o[3]);
        store4bf(Yb + row*256 + col, o[0], o[1], o[2], o[3]);
    }
}

// ---------------- head log-softmax (fp16 input) ----------------
__global__ void lsm_k(const __half* __restrict__ HP, const float* __restrict__ bo,
                      float* __restrict__ out)
{
    int w = threadIdx.x >> 5, lane = threadIdx.x & 31;
    long row = (long)blockIdx.x*8 + w;
    const __half* hp = HP + row*128;
    float v0 = __half2float(hp[lane]) + bo[lane];
    float v1 = (lane < 9) ? __half2float(hp[lane+32]) + bo[lane+32] : -INFINITY;
    float mx = fmaxf(v0, v1);
    #pragma unroll
    for (int o = 16; o; o >>= 1) mx = fmaxf(mx, __shfl_xor_sync(0xffffffffu, mx, o));
    float se = __expf(v0 - mx) + (lane < 9 ? __expf(v1 - mx) : 0.f);
    se = warp_sum(se);
    float lse = mx + logf(se);
    out[row*OUTD + lane] = v0 - lse;
    if (lane < 9) out[row*OUTD + lane + 32] = v1 - lse;
}

// ---------------- host ----------------
extern "C" void kernel_launch(void* const* d_in, const int* in_sizes, int n_in,
                              void* d_out, int out_size)
{
    (void)in_sizes; (void)n_in; (void)out_size;
    const float* x         = (const float*)d_in[0];
    const int*   day_ids   = (const int*)  d_in[1];
    const float* adapter_W = (const float*)d_in[2];
    const float* adapter_b = (const float*)d_in[3];
    const float* cW1   = (const float*)d_in[4];
    const float* cb1   = (const float*)d_in[5];
    const float* cln1s = (const float*)d_in[6];
    const float* cln1b = (const float*)d_in[7];
    const float* cW2   = (const float*)d_in[8];
    const float* cb2   = (const float*)d_in[9];
    const float* cln2s = (const float*)d_in[10];
    const float* cln2b = (const float*)d_in[11];
    const float* m_in    = (const float*)d_in[12];
    const float* m_convK = (const float*)d_in[13];
    const float* m_convB = (const float*)d_in[14];
    const float* m_dtW   = (const float*)d_in[15];
    const float* m_dtB   = (const float*)d_in[16];
    const float* m_out   = (const float*)d_in[17];
    const float* proj_W  = (const float*)d_in[18];
    const float* proj_b  = (const float*)d_in[19];
    const float* norm_s  = (const float*)d_in[20];
    const float* norm_b  = (const float*)d_in[21];
    const float* outW    = (const float*)d_in[22];
    const float* outb    = (const float*)d_in[23];
    float* out = (float*)d_out;

    static bf16 *p_xb=nullptr, *p_h512b=nullptr, *p_hb=nullptr, *p_xz=nullptr,
                *p_xc=nullptr, *p_aWb=nullptr, *p_cW1b=nullptr, *p_cW2b=nullptr,
                *p_minb=nullptr, *p_dtWb=nullptr, *p_projb=nullptr, *p_moutA=nullptr,
                *p_wcomb=nullptr, *p_wpadb=nullptr;
    static __half *p_dt=nullptr, *p_bufA=nullptr, *p_hout=nullptr;
    static float *p_h=nullptr, *p_part=nullptr;
    if (!p_xb) {
        cudaGetSymbolAddress((void**)&p_xb,    g_xb);
        cudaGetSymbolAddress((void**)&p_h512b, g_h512b);
        cudaGetSymbolAddress((void**)&p_bufA,  g_bufA);
        cudaGetSymbolAddress((void**)&p_h,     g_h);
        cudaGetSymbolAddress((void**)&p_hb,    g_hb);
        cudaGetSymbolAddress((void**)&p_xz,    g_xz);
        cudaGetSymbolAddress((void**)&p_xc,    g_xc);
        cudaGetSymbolAddress((void**)&p_dt,    g_dt);
        cudaGetSymbolAddress((void**)&p_part,  g_part);
        cudaGetSymbolAddress((void**)&p_hout,  g_hout);
        cudaGetSymbolAddress((void**)&p_aWb,   g_aWb);
        cudaGetSymbolAddress((void**)&p_cW1b,  g_cW1b);
        cudaGetSymbolAddress((void**)&p_cW2b,  g_cW2b);
        cudaGetSymbolAddress((void**)&p_minb,  g_minb);
        cudaGetSymbolAddress((void**)&p_dtWb,  g_dtWb);
        cudaGetSymbolAddress((void**)&p_projb, g_projb);
        cudaGetSymbolAddress((void**)&p_moutA, g_moutA);
        cudaGetSymbolAddress((void**)&p_wcomb, g_wcomb);
        cudaGetSymbolAddress((void**)&p_wpadb, g_wpadb);
        cudaFuncSetAttribute(tgemm_k, cudaFuncAttributeMaxDynamicSharedMemorySize,
                             SMEM_BYTES);
    }

    auto gemm = [&](const bf16* A, int lda,
                    const bf16* W, const float* bias,
                    const int* days, long wstride, int bstride,
                    void* C, int ldc, int coff,
                    int M, int K, int N, int epi, int cty,
                    int nz, int zA, long zW, int zBias, int zC, int zPart) {
        dim3 grid(N/BN, M/BM, nz);
        tgemm_k<<<grid, 256, SMEM_BYTES>>>(A, lda, W, bias, days, wstride, bstride,
                                           C, ldc, coff, K, N, epi, cty, p_part,
                                           zA, zW, zBias, zC, zPart);
    };

    // ---- conversions ----
    dim3 tb(32, 8);
    cvt_x_k<<<(BT*DIN/4)/256, 256>>>(x, p_xb);
    tconv_k<<<dim3(16,16,45), tb>>>(adapter_W, p_aWb, 512, 512);
    tconv_k<<<dim3(8,16,1),   tb>>>(cW1, p_cW1b, 512, 256);
    tconv_k<<<dim3(8,8,1),    tb>>>(cW2, p_cW2b, 256, 256);
    tconv_k<<<dim3(32,8,6),   tb>>>(m_in, p_minb, 256, 1024);
    tconv_k<<<dim3(16,16,6),  tb>>>(m_dtW, p_dtWb, 512, 512);
    tconv_k<<<dim3(8,16,3),   tb>>>(proj_W, p_projb, 512, 256);
    cvt_x_k<<<(6*512*256/4)/256, 256>>>(m_out, p_moutA);
    wpad_k<<<128, 256>>>(outW, p_wpadb);

    // ---- fused weight products ----
    for (int l = 0; l < L_; ++l)
        for (int dir = 0; dir < 2; ++dir)
            gemm(p_projb + (long)l*256*512 + dir*256, 512,
                 p_moutA + (long)(l*2+dir)*512*256, nullptr, nullptr, 0, 0,
                 p_wcomb + (long)l*256*1024, 1024, dir*512,
                 256, 256, 512, 0, 1, 1, 0,0,0,0,0);

    // 1) adapter
    gemm(p_xb, 512, p_aWb, adapter_b, day_ids, 512L*512, 512,
         p_h512b, 512, 0, BT, 512, 512, 1, 1, 1, 0,0,0,0,0);
    // 2) stem
    gemm(p_h512b, 512, p_cW1b, cb1, nullptr,0,0, p_bufA, 256, 0,
         BT, 512, 256, 0, 2, 1, 0,0,0,0,0);
    ln_k<<<BT/8, 256>>>(p_bufA, nullptr, cln1s, cln1b, nullptr, p_hb, 1);
    gemm(p_hb, 256, p_cW2b, cb2, nullptr,0,0, p_bufA, 256, 0,
         BT, 256, 256, 0, 2, 1, 0,0,0,0,0);
    ln_k<<<BT/8, 256>>>(p_bufA, nullptr, cln2s, cln2b, p_h, p_hb, 1);

    // 3) layers
    for (int l = 0; l < L_; ++l) {
        gemm(p_hb, 256, p_minb + (long)l*2048*256, nullptr, nullptr,0,0,
             p_xz, 2048, 0, BT, 256, 2048, 4, 1, 1, 0,0,0,0,0);
        conv_silu_k<<<(BT*64)/256, 256>>>(p_xz,
            m_convK + (long)l*2*512*4, m_convB + (long)l*2*512, p_xc);
        gemm(p_xc, 1024, p_dtWb + (long)l*2*512*512, m_dtB + (long)l*1024,
             nullptr,0,0, p_dt, 1024, 0, BT, 512, 512, 3, 2,
             2, 512, 512L*512, 512, 512, 512);
        scan3_k<<<512, 256>>>(p_dt, p_xz, p_xc, p_part);
        gemm(p_xc, 1024, p_wcomb + (long)l*256*1024, proj_b + l*256,
             nullptr,0,0, p_bufA, 256, 0, BT, 1024, 256, 0, 2, 1, 0,0,0,0,0);
        ln_k<<<BT/8, 256>>>(p_bufA, p_h, norm_s + l*256, norm_b + l*256,
                            p_h, p_hb, 0);
    }

    // 4) head
    gemm(p_hb, 256, p_wpadb, nullptr, nullptr,0,0, p_hout, 128, 0,
         BT, 256, 128, 0, 2, 1, 0,0,0,0,0);
    lsm_k<<<BT/8, 256>>>(p_hout, outb, out);
}